// round 1
// baseline (speedup 1.0000x reference)
#include <cuda_runtime.h>
#include <cuda_bf16.h>
#include <math.h>

// Problem constants
#define NUM_V 32
#define NUM_K 16
#define DK 128
#define DV 128
#define KW 4            // conv kernel width
#define H 2048
#define L 24
#define LI 0
#define KEY_DIM   (NUM_K * DK)          // 2048
#define VALUE_DIM (NUM_V * DV)          // 4096
#define CONV_DIM  (2 * KEY_DIM + VALUE_DIM)  // 8192

// Output layout in d_out (tuple order, flattened):
//   [0, 2048)                      hidden_out
//   [2048, 2048+786432)            new_conv_states  (24,1,8192,4)
//   [2048+786432, +12582912)       new_rec_states   (24,32,128,128)
#define OUT_HID_OFF  0
#define OUT_CONV_OFF 2048
#define CONV_ELEMS   (L * CONV_DIM * KW)          // 786432
#define OUT_REC_OFF  (2048 + CONV_ELEMS)
#define REC_LAYER    (NUM_V * DK * DV)            // 524288
#define CONV_LAYER   (CONV_DIM * KW)              // 32768

// Scratch (static device globals; no allocation allowed)
__device__ float g_mixed_qkv[CONV_DIM];
__device__ float g_z[VALUE_DIM];
__device__ float g_b[NUM_V];
__device__ float g_a[NUM_V];
__device__ float g_attn[VALUE_DIM];

// ---------------------------------------------------------------------------
// Kernel A: bulk copy of untouched layers (conv layers 1..23, rec layers 1..23)
// ---------------------------------------------------------------------------
#define NCONV4 ((CONV_ELEMS - CONV_LAYER) / 4)     // 188416
#define NREC4  ((L - 1) * REC_LAYER / 4)           // 3014656
#define NCOPY4 (NCONV4 + NREC4)

__global__ void copy_rest_kernel(const float4* __restrict__ conv_in,
                                 const float4* __restrict__ rec_in,
                                 float4* __restrict__ conv_out,
                                 float4* __restrict__ rec_out) {
    long i = (long)blockIdx.x * blockDim.x + threadIdx.x;
    if (i < NCONV4) {
        long j = (CONV_LAYER / 4) + i;   // start at layer 1
        conv_out[j] = conv_in[j];
    } else if (i < NCOPY4) {
        long j = (REC_LAYER / 4) + (i - NCONV4);
        rec_out[j] = rec_in[j];
    }
}

// ---------------------------------------------------------------------------
// Kernel B: fused mat-vec for w_qkv (8192), w_z (4096), w_b (32), w_a (32)
// one warp per row, 2048 cols, h staged in shared
// ---------------------------------------------------------------------------
#define MV_ROWS (CONV_DIM + VALUE_DIM + NUM_V + NUM_V)  // 12352
__global__ void matvec_in_kernel(const float* __restrict__ w_qkv,
                                 const float* __restrict__ w_z,
                                 const float* __restrict__ w_b,
                                 const float* __restrict__ w_a,
                                 const float* __restrict__ h) {
    __shared__ float sh[H];
    for (int i = threadIdx.x; i < H; i += blockDim.x) sh[i] = h[i];
    __syncthreads();

    int warp = (blockIdx.x * blockDim.x + threadIdx.x) >> 5;
    int lane = threadIdx.x & 31;
    if (warp >= MV_ROWS) return;

    const float* W;
    float* out;
    if (warp < CONV_DIM)                      { W = w_qkv + (size_t)warp * H;              out = &g_mixed_qkv[warp]; }
    else if (warp < CONV_DIM + VALUE_DIM)     { int r = warp - CONV_DIM; W = w_z + (size_t)r * H; out = &g_z[r]; }
    else if (warp < CONV_DIM + VALUE_DIM + NUM_V) { int r = warp - CONV_DIM - VALUE_DIM; W = w_b + (size_t)r * H; out = &g_b[r]; }
    else                                      { int r = warp - CONV_DIM - VALUE_DIM - NUM_V; W = w_a + (size_t)r * H; out = &g_a[r]; }

    const float4* W4 = (const float4*)W;
    const float4* h4 = (const float4*)sh;
    float acc = 0.f;
#pragma unroll
    for (int i = 0; i < H / 128; i++) {       // 16 iters
        int c = i * 32 + lane;
        float4 w = W4[c];
        float4 x = h4[c];
        acc = fmaf(w.x, x.x, acc);
        acc = fmaf(w.y, x.y, acc);
        acc = fmaf(w.z, x.z, acc);
        acc = fmaf(w.w, x.w, acc);
    }
#pragma unroll
    for (int o = 16; o; o >>= 1) acc += __shfl_xor_sync(0xffffffffu, acc, o);
    if (lane == 0) *out = acc;
}

// ---------------------------------------------------------------------------
// Kernel D: per value-head update. 32 blocks x 128 threads.
// Does: conv window + silu for this head's q/k/v channels, writes conv state,
// l2-norms, gates, 2-pass rec update, RMS norm, z-gate.
// ---------------------------------------------------------------------------
__device__ __forceinline__ float siluf(float x) { return x / (1.f + expf(-x)); }

__device__ __forceinline__ float block_sum_128(float v, volatile float* red) {
#pragma unroll
    for (int o = 16; o; o >>= 1) v += __shfl_xor_sync(0xffffffffu, v, o);
    int w = threadIdx.x >> 5;
    if ((threadIdx.x & 31) == 0) red[w] = v;
    __syncthreads();
    float s = red[0] + red[1] + red[2] + red[3];
    __syncthreads();
    return s;
}

__global__ void head_update_kernel(const float* __restrict__ conv_states,
                                   const float* __restrict__ rec_states,
                                   const float* __restrict__ conv_w,
                                   const float* __restrict__ dt_bias,
                                   const float* __restrict__ A_log,
                                   const float* __restrict__ norm_w,
                                   float* __restrict__ d_out) {
    __shared__ float qn[DK];
    __shared__ float kn[DK];
    __shared__ float red[4];

    const int head = blockIdx.x;
    const int t    = threadIdx.x;       // 0..127
    const int kqh  = head >> 1;         // V_PER_K = 2

    // conv for this thread's q/k/v channels
    const int cq = kqh * DK + t;
    const int ck = KEY_DIM + kqh * DK + t;
    const int cv = 2 * KEY_DIM + head * DV + t;

    float* conv_out_dst = d_out + OUT_CONV_OFF;   // layer LI=0 at offset 0

    float qraw, kraw, vval;
    {
        int chans[3] = {cq, ck, cv};
        float res[3];
#pragma unroll
        for (int j = 0; j < 3; j++) {
            int c = chans[j];
            float cs1 = conv_states[c * KW + 1];
            float cs2 = conv_states[c * KW + 2];
            float cs3 = conv_states[c * KW + 3];
            float mq  = g_mixed_qkv[c];
            float d = cs1 * conv_w[c * KW + 0] + cs2 * conv_w[c * KW + 1]
                    + cs3 * conv_w[c * KW + 2] + mq  * conv_w[c * KW + 3];
            res[j] = siluf(d);
            // write shifted conv state (q/k chans written twice by paired
            // blocks with identical values — benign)
            conv_out_dst[c * KW + 0] = cs1;
            conv_out_dst[c * KW + 1] = cs2;
            conv_out_dst[c * KW + 2] = cs3;
            conv_out_dst[c * KW + 3] = mq;
        }
        qraw = res[0]; kraw = res[1]; vval = res[2];
    }

    // l2 norms over DK (block-wide)
    float ssq_q = block_sum_128(qraw * qraw, red);
    float ssq_k = block_sum_128(kraw * kraw, red);
    qn[t] = qraw * rsqrtf(ssq_q + 1e-6f) * 0.08838834764831845f;  // 1/sqrt(128)
    kn[t] = kraw * rsqrtf(ssq_k + 1e-6f);
    __syncthreads();

    // gates (all threads compute; cheap)
    float bv = g_b[head];
    float av = g_a[head];
    float beta = 1.f / (1.f + expf(-bv));
    float x = av + dt_bias[head];
    float sp = (x > 20.f) ? x : log1pf(expf(x));
    float ge = expf(-expf(A_log[head]) * sp);

    const float* rec_in  = rec_states + (size_t)head * DK * DV;   // layer LI=0
    float*       rec_out = d_out + OUT_REC_OFF + (size_t)head * DK * DV;

    // pass 1: kv_mem (column t across k)
    float kv = 0.f;
#pragma unroll 8
    for (int k = 0; k < DK; k++) kv = fmaf(rec_in[k * DV + t], kn[k], kv);
    kv *= ge;
    float delta = (vval - kv) * beta;

    // pass 2: rec update + core (rec_in re-read hits L2)
    float core = 0.f;
#pragma unroll 8
    for (int k = 0; k < DK; k++) {
        float rn = fmaf(kn[k], delta, rec_in[k * DV + t] * ge);
        rec_out[k * DV + t] = rn;
        core = fmaf(rn, qn[k], core);
    }

    // RMS norm over DV + z gate
    float ms = block_sum_128(core * core, red) * (1.f / DV);
    float xn = core * rsqrtf(ms + 1e-6f) * norm_w[t];
    float zv = g_z[head * DV + t];
    g_attn[head * DV + t] = xn * siluf(zv);
}

// ---------------------------------------------------------------------------
// Kernel E: hidden_out = w_out @ attn  (2048 x 4096), warp per row
// ---------------------------------------------------------------------------
__global__ void matvec_out_kernel(const float* __restrict__ w_out,
                                  float* __restrict__ d_out) {
    __shared__ float sh[VALUE_DIM];
    for (int i = threadIdx.x; i < VALUE_DIM; i += blockDim.x) sh[i] = g_attn[i];
    __syncthreads();

    int warp = (blockIdx.x * blockDim.x + threadIdx.x) >> 5;
    int lane = threadIdx.x & 31;
    if (warp >= H) return;

    const float4* W4 = (const float4*)(w_out + (size_t)warp * VALUE_DIM);
    const float4* x4 = (const float4*)sh;
    float acc = 0.f;
#pragma unroll
    for (int i = 0; i < VALUE_DIM / 128; i++) {   // 32 iters
        int c = i * 32 + lane;
        float4 w = W4[c];
        float4 x = x4[c];
        acc = fmaf(w.x, x.x, acc);
        acc = fmaf(w.y, x.y, acc);
        acc = fmaf(w.z, x.z, acc);
        acc = fmaf(w.w, x.w, acc);
    }
#pragma unroll
    for (int o = 16; o; o >>= 1) acc += __shfl_xor_sync(0xffffffffu, acc, o);
    if (lane == 0) d_out[OUT_HID_OFF + warp] = acc;
}

// ---------------------------------------------------------------------------
extern "C" void kernel_launch(void* const* d_in, const int* in_sizes, int n_in,
                              void* d_out, int out_size) {
    const float* hidden_in   = (const float*)d_in[0];
    const float* conv_states = (const float*)d_in[1];
    const float* rec_states  = (const float*)d_in[2];
    const float* w_qkv       = (const float*)d_in[3];
    const float* w_z         = (const float*)d_in[4];
    const float* w_b         = (const float*)d_in[5];
    const float* w_a         = (const float*)d_in[6];
    const float* w_out       = (const float*)d_in[7];
    const float* conv_w      = (const float*)d_in[8];
    const float* dt_bias     = (const float*)d_in[9];
    const float* A_log       = (const float*)d_in[10];
    const float* norm_w      = (const float*)d_in[11];
    float* out = (float*)d_out;

    // A: bulk copy of layers 1..23 (independent of everything else)
    {
        int threads = 256;
        int blocks = (NCOPY4 + threads - 1) / threads;
        copy_rest_kernel<<<blocks, threads>>>(
            (const float4*)conv_states, (const float4*)rec_states,
            (float4*)(out + OUT_CONV_OFF), (float4*)(out + OUT_REC_OFF));
    }

    // B: input mat-vecs
    {
        int threads = 256;                       // 8 warps
        int blocks = (MV_ROWS + 7) / 8;          // 1544
        matvec_in_kernel<<<blocks, threads>>>(w_qkv, w_z, w_b, w_a, hidden_in);
    }

    // D: per-head recurrent update
    head_update_kernel<<<NUM_V, DK>>>(conv_states, rec_states, conv_w,
                                      dt_bias, A_log, norm_w, out);

    // E: output mat-vec
    {
        int threads = 256;
        int blocks = (H + 7) / 8;                // 256
        matvec_out_kernel<<<blocks, threads>>>(w_out, out);
    }
}

// round 4
// speedup vs baseline: 1.3207x; 1.3207x over previous
#include <cuda_runtime.h>
#include <cuda_bf16.h>
#include <math.h>

// Problem constants
#define NUM_V 32
#define NUM_K 16
#define DK 128
#define DV 128
#define KW 4
#define H 2048
#define L 24
#define KEY_DIM   (NUM_K * DK)               // 2048
#define VALUE_DIM (NUM_V * DV)               // 4096
#define CONV_DIM  (2 * KEY_DIM + VALUE_DIM)  // 8192

// Output layout
#define OUT_HID_OFF  0
#define OUT_CONV_OFF 2048
#define CONV_ELEMS   (L * CONV_DIM * KW)     // 786432
#define OUT_REC_OFF  (2048 + CONV_ELEMS)
#define REC_LAYER    (NUM_V * DK * DV)       // 524288
#define CONV_LAYER   (CONV_DIM * KW)         // 32768

// Copy space (float4 units), layers 1..23 of conv + rec
#define NCONV4 ((CONV_ELEMS - CONV_LAYER) / 4)   // 188416
#define NREC4  ((L - 1) * REC_LAYER / 4)         // 3014656
#define NCOPY4 (NCONV4 + NREC4)                  // 3203072
#define SPLIT4 560000                            // copy A handled by kernel1

// grid config
#define BC1 256          // copy blocks in kernel1
#define MV1_BLOCKS 1544  // matvec_in blocks (8 warps each -> 12352 rows)
#define BC3 1024         // copy blocks in kernel3
#define MV3_BLOCKS 256   // matvec_out blocks (8 warps each -> 2048 rows)
#define MV_ROWS (CONV_DIM + VALUE_DIM + NUM_V + NUM_V)  // 12352

// Scratch
__device__ float g_mixed_qkv[CONV_DIM];
__device__ float g_z[VALUE_DIM];
__device__ float g_b[NUM_V];
__device__ float g_a[NUM_V];
__device__ float g_attn[VALUE_DIM];

// ---------------------------------------------------------------------------
// Grid-stride copy over combined copy space [start4, end4)
// ---------------------------------------------------------------------------
__device__ __forceinline__ void copy_span(const float4* __restrict__ conv_in,
                                          const float4* __restrict__ rec_in,
                                          float4* __restrict__ conv_out,
                                          float4* __restrict__ rec_out,
                                          long start4, long end4,
                                          int cb, int nblocks) {
    long stride = (long)nblocks * blockDim.x;
    for (long i = start4 + (long)cb * blockDim.x + threadIdx.x; i < end4; i += stride) {
        if (i < NCONV4) {
            long j = (CONV_LAYER / 4) + i;
            __stcs(&conv_out[j], __ldcs(&conv_in[j]));
        } else {
            long j = (REC_LAYER / 4) + (i - NCONV4);
            __stcs(&rec_out[j], __ldcs(&rec_in[j]));
        }
    }
}

// ---------------------------------------------------------------------------
// Kernel 1: copy part A  +  input mat-vecs (w_qkv, w_z, w_b, w_a)
// ---------------------------------------------------------------------------
__global__ void __launch_bounds__(256) fused_in_kernel(
        const float* __restrict__ w_qkv, const float* __restrict__ w_z,
        const float* __restrict__ w_b,   const float* __restrict__ w_a,
        const float* __restrict__ h,
        const float4* __restrict__ conv_in, const float4* __restrict__ rec_in,
        float4* __restrict__ conv_out, float4* __restrict__ rec_out) {
    if (blockIdx.x < BC1) {
        copy_span(conv_in, rec_in, conv_out, rec_out, 0, SPLIT4, blockIdx.x, BC1);
        return;
    }
    __shared__ float sh[H];
    for (int i = threadIdx.x; i < H; i += blockDim.x) sh[i] = h[i];
    __syncthreads();

    int mvb  = blockIdx.x - BC1;
    int warp = mvb * 8 + (threadIdx.x >> 5);
    int lane = threadIdx.x & 31;
    if (warp >= MV_ROWS) return;

    const float* W;
    float* out;
    if (warp < CONV_DIM)                        { W = w_qkv + (size_t)warp * H; out = &g_mixed_qkv[warp]; }
    else if (warp < CONV_DIM + VALUE_DIM)       { int r = warp - CONV_DIM; W = w_z + (size_t)r * H; out = &g_z[r]; }
    else if (warp < CONV_DIM + VALUE_DIM + NUM_V) { int r = warp - CONV_DIM - VALUE_DIM; W = w_b + (size_t)r * H; out = &g_b[r]; }
    else                                        { int r = warp - CONV_DIM - VALUE_DIM - NUM_V; W = w_a + (size_t)r * H; out = &g_a[r]; }

    const float4* W4 = (const float4*)W;
    const float4* h4 = (const float4*)sh;
    float acc = 0.f;
#pragma unroll
    for (int i = 0; i < 4; i++) {               // 16 float4 total, batches of 4
        int c = i * 128 + lane;
        float4 w0 = __ldcs(&W4[c]);
        float4 w1 = __ldcs(&W4[c + 32]);
        float4 w2 = __ldcs(&W4[c + 64]);
        float4 w3 = __ldcs(&W4[c + 96]);
        float4 x0 = h4[c];
        float4 x1 = h4[c + 32];
        float4 x2 = h4[c + 64];
        float4 x3 = h4[c + 96];
        acc = fmaf(w0.x, x0.x, acc); acc = fmaf(w0.y, x0.y, acc);
        acc = fmaf(w0.z, x0.z, acc); acc = fmaf(w0.w, x0.w, acc);
        acc = fmaf(w1.x, x1.x, acc); acc = fmaf(w1.y, x1.y, acc);
        acc = fmaf(w1.z, x1.z, acc); acc = fmaf(w1.w, x1.w, acc);
        acc = fmaf(w2.x, x2.x, acc); acc = fmaf(w2.y, x2.y, acc);
        acc = fmaf(w2.z, x2.z, acc); acc = fmaf(w2.w, x2.w, acc);
        acc = fmaf(w3.x, x3.x, acc); acc = fmaf(w3.y, x3.y, acc);
        acc = fmaf(w3.z, x3.z, acc); acc = fmaf(w3.w, x3.w, acc);
    }
#pragma unroll
    for (int o = 16; o; o >>= 1) acc += __shfl_xor_sync(0xffffffffu, acc, o);
    if (lane == 0) *out = acc;
}

// ---------------------------------------------------------------------------
// Kernel 2: per value-head recurrent update (32 blocks x 128 threads)
// ---------------------------------------------------------------------------
__device__ __forceinline__ float siluf(float x) { return x / (1.f + expf(-x)); }

__device__ __forceinline__ float block_sum_128(float v, volatile float* red) {
#pragma unroll
    for (int o = 16; o; o >>= 1) v += __shfl_xor_sync(0xffffffffu, v, o);
    int w = threadIdx.x >> 5;
    if ((threadIdx.x & 31) == 0) red[w] = v;
    __syncthreads();
    float s = red[0] + red[1] + red[2] + red[3];
    __syncthreads();
    return s;
}

__global__ void head_update_kernel(const float* __restrict__ conv_states,
                                   const float* __restrict__ rec_states,
                                   const float* __restrict__ conv_w,
                                   const float* __restrict__ dt_bias,
                                   const float* __restrict__ A_log,
                                   const float* __restrict__ norm_w,
                                   float* __restrict__ d_out) {
    __shared__ float qn[DK];
    __shared__ float kn[DK];
    __shared__ float red[4];

    const int head = blockIdx.x;
    const int t    = threadIdx.x;
    const int kqh  = head >> 1;

    const int cq = kqh * DK + t;
    const int ck = KEY_DIM + kqh * DK + t;
    const int cv = 2 * KEY_DIM + head * DV + t;

    float* conv_out_dst = d_out + OUT_CONV_OFF;

    float qraw, kraw, vval;
    {
        int chans[3] = {cq, ck, cv};
        float res[3];
#pragma unroll
        for (int j = 0; j < 3; j++) {
            int c = chans[j];
            float cs1 = conv_states[c * KW + 1];
            float cs2 = conv_states[c * KW + 2];
            float cs3 = conv_states[c * KW + 3];
            float mq  = g_mixed_qkv[c];
            float d = cs1 * conv_w[c * KW + 0] + cs2 * conv_w[c * KW + 1]
                    + cs3 * conv_w[c * KW + 2] + mq  * conv_w[c * KW + 3];
            res[j] = siluf(d);
            conv_out_dst[c * KW + 0] = cs1;
            conv_out_dst[c * KW + 1] = cs2;
            conv_out_dst[c * KW + 2] = cs3;
            conv_out_dst[c * KW + 3] = mq;
        }
        qraw = res[0]; kraw = res[1]; vval = res[2];
    }

    float ssq_q = block_sum_128(qraw * qraw, red);
    float ssq_k = block_sum_128(kraw * kraw, red);
    qn[t] = qraw * rsqrtf(ssq_q + 1e-6f) * 0.08838834764831845f;
    kn[t] = kraw * rsqrtf(ssq_k + 1e-6f);
    __syncthreads();

    float bv = g_b[head];
    float av = g_a[head];
    float beta = 1.f / (1.f + expf(-bv));
    float x = av + dt_bias[head];
    float sp = (x > 20.f) ? x : log1pf(expf(x));
    float ge = expf(-expf(A_log[head]) * sp);

    const float* rec_in  = rec_states + (size_t)head * DK * DV;
    float*       rec_out = d_out + OUT_REC_OFF + (size_t)head * DK * DV;

    float kv = 0.f;
#pragma unroll 8
    for (int k = 0; k < DK; k++) kv = fmaf(rec_in[k * DV + t], kn[k], kv);
    kv *= ge;
    float delta = (vval - kv) * beta;

    float core = 0.f;
#pragma unroll 8
    for (int k = 0; k < DK; k++) {
        float rn = fmaf(kn[k], delta, rec_in[k * DV + t] * ge);
        rec_out[k * DV + t] = rn;
        core = fmaf(rn, qn[k], core);
    }

    float ms = block_sum_128(core * core, red) * (1.f / DV);
    float xn = core * rsqrtf(ms + 1e-6f) * norm_w[t];
    float zv = g_z[head * DV + t];
    g_attn[head * DV + t] = xn * siluf(zv);
}

// ---------------------------------------------------------------------------
// Kernel 3: copy part B  +  hidden_out = w_out @ attn
// ---------------------------------------------------------------------------
__global__ void __launch_bounds__(256) fused_out_kernel(
        const float* __restrict__ w_out, float* __restrict__ d_out,
        const float4* __restrict__ conv_in, const float4* __restrict__ rec_in,
        float4* __restrict__ conv_out, float4* __restrict__ rec_out) {
    if (blockIdx.x < BC3) {
        copy_span(conv_in, rec_in, conv_out, rec_out, SPLIT4, NCOPY4, blockIdx.x, BC3);
        return;
    }
    __shared__ float sh[VALUE_DIM];
    for (int i = threadIdx.x; i < VALUE_DIM; i += blockDim.x) sh[i] = g_attn[i];
    __syncthreads();

    int mvb  = blockIdx.x - BC3;
    int warp = mvb * 8 + (threadIdx.x >> 5);
    int lane = threadIdx.x & 31;
    if (warp >= H) return;

    const float4* W4 = (const float4*)(w_out + (size_t)warp * VALUE_DIM);
    const float4* x4 = (const float4*)sh;
    float acc = 0.f;
#pragma unroll
    for (int i = 0; i < 8; i++) {               // 32 float4 total, batches of 4
        int c = i * 128 + lane;
        float4 w0 = __ldcs(&W4[c]);
        float4 w1 = __ldcs(&W4[c + 32]);
        float4 w2 = __ldcs(&W4[c + 64]);
        float4 w3 = __ldcs(&W4[c + 96]);
        float4 x0 = x4[c];
        float4 x1 = x4[c + 32];
        float4 x2 = x4[c + 64];
        float4 x3 = x4[c + 96];
        acc = fmaf(w0.x, x0.x, acc); acc = fmaf(w0.y, x0.y, acc);
        acc = fmaf(w0.z, x0.z, acc); acc = fmaf(w0.w, x0.w, acc);
        acc = fmaf(w1.x, x1.x, acc); acc = fmaf(w1.y, x1.y, acc);
        acc = fmaf(w1.z, x1.z, acc); acc = fmaf(w1.w, x1.w, acc);
        acc = fmaf(w2.x, x2.x, acc); acc = fmaf(w2.y, x2.y, acc);
        acc = fmaf(w2.z, x2.z, acc); acc = fmaf(w2.w, x2.w, acc);
        acc = fmaf(w3.x, x3.x, acc); acc = fmaf(w3.y, x3.y, acc);
        acc = fmaf(w3.z, x3.z, acc); acc = fmaf(w3.w, x3.w, acc);
    }
#pragma unroll
    for (int o = 16; o; o >>= 1) acc += __shfl_xor_sync(0xffffffffu, acc, o);
    if (lane == 0) d_out[OUT_HID_OFF + warp] = acc;
}

// ---------------------------------------------------------------------------
extern "C" void kernel_launch(void* const* d_in, const int* in_sizes, int n_in,
                              void* d_out, int out_size) {
    const float* hidden_in   = (const float*)d_in[0];
    const float* conv_states = (const float*)d_in[1];
    const float* rec_states  = (const float*)d_in[2];
    const float* w_qkv       = (const float*)d_in[3];
    const float* w_z         = (const float*)d_in[4];
    const float* w_b         = (const float*)d_in[5];
    const float* w_a         = (const float*)d_in[6];
    const float* w_out       = (const float*)d_in[7];
    const float* conv_w      = (const float*)d_in[8];
    const float* dt_bias     = (const float*)d_in[9];
    const float* A_log       = (const float*)d_in[10];
    const float* norm_w      = (const float*)d_in[11];
    float* out = (float*)d_out;

    fused_in_kernel<<<BC1 + MV1_BLOCKS, 256>>>(
        w_qkv, w_z, w_b, w_a, hidden_in,
        (const float4*)conv_states, (const float4*)rec_states,
        (float4*)(out + OUT_CONV_OFF), (float4*)(out + OUT_REC_OFF));

    head_update_kernel<<<NUM_V, DK>>>(conv_states, rec_states, conv_w,
                                      dt_bias, A_log, norm_w, out);

    fused_out_kernel<<<BC3 + MV3_BLOCKS, 256>>>(
        w_out, out,
        (const float4*)conv_states, (const float4*)rec_states,
        (float4*)(out + OUT_CONV_OFF), (float4*)(out + OUT_REC_OFF));
}